// round 5
// baseline (speedup 1.0000x reference)
#include <cuda_runtime.h>
#include <cstdint>

// PlaneModel: B=8192, NV=8 (512 voxels), P=64, NS=32, HID1=16, BASE=32, OUT=13, D_IN=79
#define FULL 0xffffffffu
typedef unsigned long long u64;

__device__ __forceinline__ u64 dup2(float a){
    u64 r; asm("mov.b64 %0,{%1,%1};" : "=l"(r) : "f"(a)); return r;
}
__device__ __forceinline__ void upk2(u64 v, float& a, float& b){
    asm("mov.b64 {%0,%1},%2;" : "=f"(a), "=f"(b) : "l"(v));
}
__device__ __forceinline__ void fma2(u64& d, u64 a, u64 b){
    asm("fma.rn.f32x2 %0,%1,%2,%0;" : "+l"(d) : "l"(a), "l"(b));
}

__device__ __forceinline__ float wsum(float x){
    x += __shfl_xor_sync(FULL, x, 16);
    x += __shfl_xor_sync(FULL, x, 8);
    x += __shfl_xor_sync(FULL, x, 4);
    x += __shfl_xor_sync(FULL, x, 2);
    x += __shfl_xor_sync(FULL, x, 1);
    return x;
}

// h[8] packed f32x2 accumulators += x * wrow[0..15]  (broadcast LDS.128 x4)
__device__ __forceinline__ void acc1(u64* h, float x, const float* wrow){
    u64 xx = dup2(x);
    const ulonglong2* w = (const ulonglong2*)wrow;
    #pragma unroll
    for (int t = 0; t < 4; t++){
        ulonglong2 wv = w[t];
        fma2(h[2*t],   xx, wv.x);
        fma2(h[2*t+1], xx, wv.y);
    }
}

#define ZSTRIDE 36   // 32 cols + 4 pad: STS conflict-free; LDS.128 readback conflict-free

__global__ void __launch_bounds__(256, 4)
plane_kernel(const float* __restrict__ g_pos,  const float* __restrict__ g_quat,
             const float* __restrict__ g_xz,   const float* __restrict__ g_aabb,
             const int*   __restrict__ g_widx, const float* __restrict__ g_pls,
             const float* __restrict__ g_w1,   const float* __restrict__ g_b1,
             const float* __restrict__ g_g1,   const float* __restrict__ g_be1,
             const float* __restrict__ g_w2a,  const float* __restrict__ g_b2a,
             const float* __restrict__ g_g2a,  const float* __restrict__ g_be2a,
             const float* __restrict__ g_w2b,  const float* __restrict__ g_b2b,
             const float* __restrict__ g_g2b,  const float* __restrict__ g_be2b,
             const float* __restrict__ g_wout, const float* __restrict__ g_bout,
             float* __restrict__ g_out)
{
    __shared__ __align__(16) float s_w1[79*16];
    __shared__ __align__(16) float s_b1[16];
    __shared__ float s_g1[16], s_be1[16];
    __shared__ __align__(16) float s_z[8][32*ZSTRIDE];   // 36.9 KB

    const int tid = threadIdx.x;
    for (int i = tid; i < 79*16; i += 256) s_w1[i] = g_w1[i];
    if (tid < 16){ s_b1[tid] = g_b1[tid]; s_g1[tid] = g_g1[tid]; s_be1[tid] = g_be1[tid]; }
    __syncthreads();

    const int warp = tid >> 5, lane = tid & 31;
    const int b = (blockIdx.x << 3) + warp;
    float* sz = s_z[warp];

    const int idx = __ldg(g_widx + b*32 + lane);
    const float* xzb = g_xz + ((size_t)b << 15);   // b * 512 * 64

    // ---- phase 0 staging: cols 0..31 of the 32 gathered rows (coalesced) ----
    #pragma unroll
    for (int r = 0; r < 32; r++){
        int ir = __shfl_sync(FULL, idx, r);
        sz[r*ZSTRIDE + lane] = __ldcs(xzb + (ir << 6) + lane);
    }

    // ---- pose math overlaps the staging LDG latency ----
    float qx = __ldg(g_quat + b*4 + 0), qy = __ldg(g_quat + b*4 + 1);
    float qz = __ldg(g_quat + b*4 + 2), qw = __ldg(g_quat + b*4 + 3);
    float rn = rsqrtf(qx*qx + qy*qy + qz*qz + qw*qw);
    qx *= rn; qy *= rn; qz *= rn; qw *= rn;
    float r00 = 1.f - 2.f*(qy*qy + qz*qz), r01 = 2.f*(qx*qy - qz*qw), r02 = 2.f*(qx*qz + qy*qw);
    float r10 = 2.f*(qx*qy + qz*qw), r11 = 1.f - 2.f*(qx*qx + qz*qz), r12 = 2.f*(qy*qz - qx*qw);
    float r20 = 2.f*(qx*qz - qy*qw), r21 = 2.f*(qy*qz + qx*qw), r22 = 1.f - 2.f*(qx*qx + qy*qy);

    float px = __ldg(g_pos + b*3 + 0), py = __ldg(g_pos + b*3 + 1), pz = __ldg(g_pos + b*3 + 2);
    float lox = __ldg(g_aabb + b*6 + 0), loy = __ldg(g_aabb + b*6 + 1), loz = __ldg(g_aabb + b*6 + 2);
    float hix = __ldg(g_aabb + b*6 + 3), hiy = __ldg(g_aabb + b*6 + 4), hiz = __ldg(g_aabb + b*6 + 5);

    // voxel center (meshgrid 'ij': n = i*64 + j*8 + k)
    float ci = (float)(idx >> 6)       + 0.5f;
    float cj = (float)((idx >> 3) & 7) + 0.5f;
    float ck = (float)(idx & 7)        + 0.5f;
    float vx = (ci * 0.125f) * (hix - lox) + lox;
    float vy = (cj * 0.125f) * (hiy - loy) + loy;
    float vz = (ck * 0.125f) * (hiz - loz) + loz;
    float e = expf(__ldg(g_pls));

    u64 h[8];
    #pragma unroll
    for (int t = 0; t < 8; t++) h[t] = *(const u64*)(s_b1 + 2*t);

    acc1(h, r00*vx + r01*vy + r02*vz + px, s_w1 + 0*16);
    acc1(h, r10*vx + r11*vy + r12*vz + py, s_w1 + 1*16);
    acc1(h, r20*vx + r21*vy + r22*vz + pz, s_w1 + 2*16);
    acc1(h, px*e, s_w1 + 67*16);
    acc1(h, py*e, s_w1 + 68*16);
    acc1(h, pz*e, s_w1 + 69*16);
    acc1(h, r00, s_w1 + 70*16);
    acc1(h, r01, s_w1 + 71*16);
    acc1(h, r02, s_w1 + 72*16);
    acc1(h, r10, s_w1 + 73*16);
    acc1(h, r11, s_w1 + 74*16);
    acc1(h, r12, s_w1 + 75*16);
    acc1(h, r20, s_w1 + 76*16);
    acc1(h, r21, s_w1 + 77*16);
    acc1(h, r22, s_w1 + 78*16);

    __syncwarp(FULL);

    // ---- consume phase 0 (feature rows 3..34) ----
    const float* row = sz + lane*ZSTRIDE;
    #pragma unroll
    for (int t = 0; t < 8; t++){
        float4 a = *(const float4*)(row + 4*t);
        acc1(h, a.x, s_w1 + (3 + 4*t + 0)*16);
        acc1(h, a.y, s_w1 + (3 + 4*t + 1)*16);
        acc1(h, a.z, s_w1 + (3 + 4*t + 2)*16);
        acc1(h, a.w, s_w1 + (3 + 4*t + 3)*16);
    }
    __syncwarp(FULL);

    // ---- phase 1 staging: cols 32..63 ----
    #pragma unroll
    for (int r = 0; r < 32; r++){
        int ir = __shfl_sync(FULL, idx, r);
        sz[r*ZSTRIDE + lane] = __ldcs(xzb + (ir << 6) + 32 + lane);
    }
    __syncwarp(FULL);

    // ---- consume phase 1 (feature rows 35..66) ----
    #pragma unroll
    for (int t = 0; t < 8; t++){
        float4 a = *(const float4*)(row + 4*t);
        acc1(h, a.x, s_w1 + (35 + 4*t + 0)*16);
        acc1(h, a.y, s_w1 + (35 + 4*t + 1)*16);
        acc1(h, a.z, s_w1 + (35 + 4*t + 2)*16);
        acc1(h, a.w, s_w1 + (35 + 4*t + 3)*16);
    }

    // ---- relu + LN(16) per lane, x2, butterfly-sum over the 32 samples ----
    float v[16];
    #pragma unroll
    for (int t = 0; t < 8; t++) upk2(h[t], v[2*t], v[2*t+1]);
    float m = 0.f;
    #pragma unroll
    for (int j = 0; j < 16; j++){ v[j] = fmaxf(v[j], 0.f); m += v[j]; }
    m *= 0.0625f;
    float var = 0.f;
    #pragma unroll
    for (int j = 0; j < 16; j++){ float d = v[j] - m; var += d*d; }
    var *= 0.0625f;
    float is = rsqrtf(var + 1e-6f);
    #pragma unroll
    for (int j = 0; j < 16; j++){
        float y = (v[j] - m) * is * s_g1[j] + s_be1[j];
        y += y;                                  // z = z + z
        y += __shfl_xor_sync(FULL, y, 16);
        y += __shfl_xor_sync(FULL, y, 8);
        y += __shfl_xor_sync(FULL, y, 4);
        y += __shfl_xor_sync(FULL, y, 2);
        y += __shfl_xor_sync(FULL, y, 1);
        v[j] = y;
    }

    // ---- head: lane = channel, split accumulators ----
    {
        float a0 = __ldg(g_b2a + lane), a1 = 0.f, a2 = 0.f, a3 = 0.f;
        #pragma unroll
        for (int i = 0; i < 16; i += 4){
            a0 = fmaf(v[i+0], __ldg(g_w2a + (i+0)*32 + lane), a0);
            a1 = fmaf(v[i+1], __ldg(g_w2a + (i+1)*32 + lane), a1);
            a2 = fmaf(v[i+2], __ldg(g_w2a + (i+2)*32 + lane), a2);
            a3 = fmaf(v[i+3], __ldg(g_w2a + (i+3)*32 + lane), a3);
        }
        float a = (a0 + a1) + (a2 + a3);
        a = fmaxf(a, 0.f);
        float ma = wsum(a) * 0.03125f;
        float da = a - ma;
        float va = wsum(da*da) * 0.03125f;
        float ya = da * rsqrtf(va + 1e-6f) * __ldg(g_g2a + lane) + __ldg(g_be2a + lane);

        float c0 = __ldg(g_b2b + lane), c1 = 0.f, c2 = 0.f, c3 = 0.f;
        #pragma unroll
        for (int i = 0; i < 32; i += 4){
            c0 = fmaf(__shfl_sync(FULL, ya, i+0), __ldg(g_w2b + (i+0)*32 + lane), c0);
            c1 = fmaf(__shfl_sync(FULL, ya, i+1), __ldg(g_w2b + (i+1)*32 + lane), c1);
            c2 = fmaf(__shfl_sync(FULL, ya, i+2), __ldg(g_w2b + (i+2)*32 + lane), c2);
            c3 = fmaf(__shfl_sync(FULL, ya, i+3), __ldg(g_w2b + (i+3)*32 + lane), c3);
        }
        float c = (c0 + c1) + (c2 + c3);
        c = fmaxf(c, 0.f);
        float mc = wsum(c) * 0.03125f;
        float dc = c - mc;
        float vc = wsum(dc*dc) * 0.03125f;
        float yb = dc * rsqrtf(vc + 1e-6f) * __ldg(g_g2b + lane) + __ldg(g_be2b + lane);
        float zf = yb + ya;   // residual

        float o0 = (lane < 13) ? __ldg(g_bout + lane) : 0.f;
        float o1 = 0.f;
        #pragma unroll
        for (int i = 0; i < 32; i += 2){
            float zi0 = __shfl_sync(FULL, zf, i);
            float zi1 = __shfl_sync(FULL, zf, i+1);
            if (lane < 13){
                o0 = fmaf(zi0, __ldg(g_wout + (i  )*13 + lane), o0);
                o1 = fmaf(zi1, __ldg(g_wout + (i+1)*13 + lane), o1);
            }
        }
        if (lane < 13) g_out[b*13 + lane] = tanhf(o0 + o1);
    }
}

extern "C" void kernel_launch(void* const* d_in, const int* in_sizes, int n_in,
                              void* d_out, int out_size)
{
    (void)in_sizes; (void)n_in; (void)out_size;
    plane_kernel<<<1024, 256>>>(
        (const float*)d_in[0],  (const float*)d_in[1],  (const float*)d_in[2],
        (const float*)d_in[3],  (const int*)  d_in[4],  (const float*)d_in[5],
        (const float*)d_in[6],  (const float*)d_in[7],  (const float*)d_in[8],
        (const float*)d_in[9],  (const float*)d_in[10], (const float*)d_in[11],
        (const float*)d_in[12], (const float*)d_in[13], (const float*)d_in[14],
        (const float*)d_in[15], (const float*)d_in[16], (const float*)d_in[17],
        (const float*)d_in[18], (const float*)d_in[19],
        (float*)d_out);
}

// round 6
// speedup vs baseline: 1.8712x; 1.8712x over previous
#include <cuda_runtime.h>
#include <cstdint>

// PlaneModel: B=8192, NV=8 (512 voxels), P=64, NS=32, HID1=16, BASE=32, OUT=13, D_IN=79
#define FULL 0xffffffffu
typedef unsigned long long u64;

__device__ __forceinline__ u64 dup2(float a){
    u64 r; asm("mov.b64 %0,{%1,%1};" : "=l"(r) : "f"(a)); return r;
}
__device__ __forceinline__ void upk2(u64 v, float& a, float& b){
    asm("mov.b64 {%0,%1},%2;" : "=f"(a), "=f"(b) : "l"(v));
}
__device__ __forceinline__ void fma2(u64& d, u64 a, u64 b){
    asm("fma.rn.f32x2 %0,%1,%2,%0;" : "+l"(d) : "l"(a), "l"(b));
}

__device__ __forceinline__ float wsum(float x){
    x += __shfl_xor_sync(FULL, x, 16);
    x += __shfl_xor_sync(FULL, x, 8);
    x += __shfl_xor_sync(FULL, x, 4);
    x += __shfl_xor_sync(FULL, x, 2);
    x += __shfl_xor_sync(FULL, x, 1);
    return x;
}

// h[8] packed f32x2 accumulators += x * wrow[0..15]  (broadcast LDS.128 x4)
__device__ __forceinline__ void acc1(u64* h, float x, const float* wrow){
    u64 xx = dup2(x);
    const ulonglong2* w = (const ulonglong2*)wrow;
    #pragma unroll
    for (int t = 0; t < 4; t++){
        ulonglong2 wv = w[t];
        fma2(h[2*t],   xx, wv.x);
        fma2(h[2*t+1], xx, wv.y);
    }
}

#define ZSTRIDE 68   // 64 cols + 4 pad: STS.128 and LDS.128 readback conflict-free

__global__ void __launch_bounds__(256, 3)
plane_kernel(const float* __restrict__ g_pos,  const float* __restrict__ g_quat,
             const float* __restrict__ g_xz,   const float* __restrict__ g_aabb,
             const int*   __restrict__ g_widx, const float* __restrict__ g_pls,
             const float* __restrict__ g_w1,   const float* __restrict__ g_b1,
             const float* __restrict__ g_g1,   const float* __restrict__ g_be1,
             const float* __restrict__ g_w2a,  const float* __restrict__ g_b2a,
             const float* __restrict__ g_g2a,  const float* __restrict__ g_be2a,
             const float* __restrict__ g_w2b,  const float* __restrict__ g_b2b,
             const float* __restrict__ g_g2b,  const float* __restrict__ g_be2b,
             const float* __restrict__ g_wout, const float* __restrict__ g_bout,
             float* __restrict__ g_out)
{
    extern __shared__ __align__(16) float smem[];
    float* s_w1  = smem;                 // 79*16 = 1264
    float* s_b1  = smem + 1264;          // 16
    float* s_g1  = smem + 1280;          // 16
    float* s_be1 = smem + 1296;          // 16
    float* s_z   = smem + 1312;          // 8 warps * 32*ZSTRIDE

    const int tid = threadIdx.x;
    for (int i = tid; i < 79*16; i += 256) s_w1[i] = g_w1[i];
    if (tid < 16){ s_b1[tid] = g_b1[tid]; s_g1[tid] = g_g1[tid]; s_be1[tid] = g_be1[tid]; }
    __syncthreads();

    const int warp = tid >> 5, lane = tid & 31;
    const int b = (blockIdx.x << 3) + warp;
    float* sz = s_z + warp * (32*ZSTRIDE);

    const int idx = __ldg(g_widx + b*32 + lane);
    const float* xzb = g_xz + ((size_t)b << 15);   // b * 512 * 64

    // ---- wide cooperative gather: 16 x LDG.128 stage all 32 rows x 256B ----
    // lane = (row parity in pair, 16B chunk): lanes 0-15 -> row 2i, 16-31 -> row 2i+1
    {
        const int half = lane >> 4;      // 0 or 1
        const int c    = lane & 15;      // 16B chunk 0..15
        #pragma unroll
        for (int i = 0; i < 16; i++){
            int r  = 2*i + half;
            int ir = __shfl_sync(FULL, idx, r);
            float4 val = __ldg((const float4*)(xzb + (ir << 6)) + c);
            *(float4*)(sz + r*ZSTRIDE + 4*c) = val;
        }
    }

    // ---- pose math overlaps the staging LDG latency ----
    float qx = __ldg(g_quat + b*4 + 0), qy = __ldg(g_quat + b*4 + 1);
    float qz = __ldg(g_quat + b*4 + 2), qw = __ldg(g_quat + b*4 + 3);
    float rn = rsqrtf(qx*qx + qy*qy + qz*qz + qw*qw);
    qx *= rn; qy *= rn; qz *= rn; qw *= rn;
    float r00 = 1.f - 2.f*(qy*qy + qz*qz), r01 = 2.f*(qx*qy - qz*qw), r02 = 2.f*(qx*qz + qy*qw);
    float r10 = 2.f*(qx*qy + qz*qw), r11 = 1.f - 2.f*(qx*qx + qz*qz), r12 = 2.f*(qy*qz - qx*qw);
    float r20 = 2.f*(qx*qz - qy*qw), r21 = 2.f*(qy*qz + qx*qw), r22 = 1.f - 2.f*(qx*qx + qy*qy);

    float px = __ldg(g_pos + b*3 + 0), py = __ldg(g_pos + b*3 + 1), pz = __ldg(g_pos + b*3 + 2);
    float lox = __ldg(g_aabb + b*6 + 0), loy = __ldg(g_aabb + b*6 + 1), loz = __ldg(g_aabb + b*6 + 2);
    float hix = __ldg(g_aabb + b*6 + 3), hiy = __ldg(g_aabb + b*6 + 4), hiz = __ldg(g_aabb + b*6 + 5);

    // voxel center (meshgrid 'ij': n = i*64 + j*8 + k)
    float ci = (float)(idx >> 6)       + 0.5f;
    float cj = (float)((idx >> 3) & 7) + 0.5f;
    float ck = (float)(idx & 7)        + 0.5f;
    float vx = (ci * 0.125f) * (hix - lox) + lox;
    float vy = (cj * 0.125f) * (hiy - loy) + loy;
    float vz = (ck * 0.125f) * (hiz - loz) + loz;
    float e = __expf(__ldg(g_pls));

    u64 h[8];
    #pragma unroll
    for (int t = 0; t < 8; t++) h[t] = *(const u64*)(s_b1 + 2*t);

    acc1(h, r00*vx + r01*vy + r02*vz + px, s_w1 + 0*16);
    acc1(h, r10*vx + r11*vy + r12*vz + py, s_w1 + 1*16);
    acc1(h, r20*vx + r21*vy + r22*vz + pz, s_w1 + 2*16);
    acc1(h, px*e, s_w1 + 67*16);
    acc1(h, py*e, s_w1 + 68*16);
    acc1(h, pz*e, s_w1 + 69*16);
    acc1(h, r00, s_w1 + 70*16);
    acc1(h, r01, s_w1 + 71*16);
    acc1(h, r02, s_w1 + 72*16);
    acc1(h, r10, s_w1 + 73*16);
    acc1(h, r11, s_w1 + 74*16);
    acc1(h, r12, s_w1 + 75*16);
    acc1(h, r20, s_w1 + 76*16);
    acc1(h, r21, s_w1 + 77*16);
    acc1(h, r22, s_w1 + 78*16);

    __syncwarp(FULL);

    // ---- consume 64 xz features (rows 3..66) ----
    const float* row = sz + lane*ZSTRIDE;
    #pragma unroll
    for (int t = 0; t < 16; t++){
        float4 a = *(const float4*)(row + 4*t);
        acc1(h, a.x, s_w1 + (3 + 4*t + 0)*16);
        acc1(h, a.y, s_w1 + (3 + 4*t + 1)*16);
        acc1(h, a.z, s_w1 + (3 + 4*t + 2)*16);
        acc1(h, a.w, s_w1 + (3 + 4*t + 3)*16);
    }

    // ---- relu + LN(16) per lane, x2, butterfly-sum over the 32 samples ----
    float v[16];
    #pragma unroll
    for (int t = 0; t < 8; t++) upk2(h[t], v[2*t], v[2*t+1]);
    float m = 0.f;
    #pragma unroll
    for (int j = 0; j < 16; j++){ v[j] = fmaxf(v[j], 0.f); m += v[j]; }
    m *= 0.0625f;
    float var = 0.f;
    #pragma unroll
    for (int j = 0; j < 16; j++){ float d = v[j] - m; var += d*d; }
    var *= 0.0625f;
    float is = rsqrtf(var + 1e-6f);
    #pragma unroll
    for (int j = 0; j < 16; j++){
        float y = (v[j] - m) * is * s_g1[j] + s_be1[j];
        y += y;                                  // z = z + z
        y += __shfl_xor_sync(FULL, y, 16);
        y += __shfl_xor_sync(FULL, y, 8);
        y += __shfl_xor_sync(FULL, y, 4);
        y += __shfl_xor_sync(FULL, y, 2);
        y += __shfl_xor_sync(FULL, y, 1);
        v[j] = y;
    }

    // ---- head: lane = channel, split accumulators for short chains ----
    {
        float a0 = __ldg(g_b2a + lane), a1 = 0.f, a2 = 0.f, a3 = 0.f;
        #pragma unroll
        for (int i = 0; i < 16; i += 4){
            a0 = fmaf(v[i+0], __ldg(g_w2a + (i+0)*32 + lane), a0);
            a1 = fmaf(v[i+1], __ldg(g_w2a + (i+1)*32 + lane), a1);
            a2 = fmaf(v[i+2], __ldg(g_w2a + (i+2)*32 + lane), a2);
            a3 = fmaf(v[i+3], __ldg(g_w2a + (i+3)*32 + lane), a3);
        }
        float a = (a0 + a1) + (a2 + a3);
        a = fmaxf(a, 0.f);
        float ma = wsum(a) * 0.03125f;
        float da = a - ma;
        float va = wsum(da*da) * 0.03125f;
        float ya = da * rsqrtf(va + 1e-6f) * __ldg(g_g2a + lane) + __ldg(g_be2a + lane);

        float c0 = __ldg(g_b2b + lane), c1 = 0.f, c2 = 0.f, c3 = 0.f;
        #pragma unroll
        for (int i = 0; i < 32; i += 4){
            c0 = fmaf(__shfl_sync(FULL, ya, i+0), __ldg(g_w2b + (i+0)*32 + lane), c0);
            c1 = fmaf(__shfl_sync(FULL, ya, i+1), __ldg(g_w2b + (i+1)*32 + lane), c1);
            c2 = fmaf(__shfl_sync(FULL, ya, i+2), __ldg(g_w2b + (i+2)*32 + lane), c2);
            c3 = fmaf(__shfl_sync(FULL, ya, i+3), __ldg(g_w2b + (i+3)*32 + lane), c3);
        }
        float c = (c0 + c1) + (c2 + c3);
        c = fmaxf(c, 0.f);
        float mc = wsum(c) * 0.03125f;
        float dc = c - mc;
        float vc = wsum(dc*dc) * 0.03125f;
        float yb = dc * rsqrtf(vc + 1e-6f) * __ldg(g_g2b + lane) + __ldg(g_be2b + lane);
        float zf = yb + ya;   // residual

        float o0 = (lane < 13) ? __ldg(g_bout + lane) : 0.f;
        float o1 = 0.f;
        #pragma unroll
        for (int i = 0; i < 32; i += 2){
            float zi0 = __shfl_sync(FULL, zf, i);
            float zi1 = __shfl_sync(FULL, zf, i+1);
            if (lane < 13){
                o0 = fmaf(zi0, __ldg(g_wout + (i  )*13 + lane), o0);
                o1 = fmaf(zi1, __ldg(g_wout + (i+1)*13 + lane), o1);
            }
        }
        if (lane < 13) g_out[b*13 + lane] = tanhf(o0 + o1);
    }
}

extern "C" void kernel_launch(void* const* d_in, const int* in_sizes, int n_in,
                              void* d_out, int out_size)
{
    (void)in_sizes; (void)n_in; (void)out_size;
    const int SMEM_BYTES = (1312 + 8*32*ZSTRIDE) * 4;   // ~73.1 KB (3 blocks/SM fit in 228KB)
    cudaFuncSetAttribute(plane_kernel,
                         cudaFuncAttributeMaxDynamicSharedMemorySize, SMEM_BYTES);
    plane_kernel<<<1024, 256, SMEM_BYTES>>>(
        (const float*)d_in[0],  (const float*)d_in[1],  (const float*)d_in[2],
        (const float*)d_in[3],  (const int*)  d_in[4],  (const float*)d_in[5],
        (const float*)d_in[6],  (const float*)d_in[7],  (const float*)d_in[8],
        (const float*)d_in[9],  (const float*)d_in[10], (const float*)d_in[11],
        (const float*)d_in[12], (const float*)d_in[13], (const float*)d_in[14],
        (const float*)d_in[15], (const float*)d_in[16], (const float*)d_in[17],
        (const float*)d_in[18], (const float*)d_in[19],
        (float*)d_out);
}

// round 7
// speedup vs baseline: 1.9271x; 1.0299x over previous
#include <cuda_runtime.h>
#include <cstdint>

// PlaneModel: B=8192, NV=8 (512 voxels), P=64, NS=32, HID1=16, BASE=32, OUT=13, D_IN=79
#define FULL 0xffffffffu
typedef unsigned long long u64;

__device__ __forceinline__ u64 dup2(float a){
    u64 r; asm("mov.b64 %0,{%1,%1};" : "=l"(r) : "f"(a)); return r;
}
__device__ __forceinline__ void upk2(u64 v, float& a, float& b){
    asm("mov.b64 {%0,%1},%2;" : "=f"(a), "=f"(b) : "l"(v));
}
__device__ __forceinline__ void fma2(u64& d, u64 a, u64 b){
    asm("fma.rn.f32x2 %0,%1,%2,%0;" : "+l"(d) : "l"(a), "l"(b));
}

__device__ __forceinline__ float wsum(float x){
    x += __shfl_xor_sync(FULL, x, 16);
    x += __shfl_xor_sync(FULL, x, 8);
    x += __shfl_xor_sync(FULL, x, 4);
    x += __shfl_xor_sync(FULL, x, 2);
    x += __shfl_xor_sync(FULL, x, 1);
    return x;
}

// h[8] packed f32x2 accumulators += x * wrow[0..15]  (broadcast LDS.128 x4)
__device__ __forceinline__ void acc1(u64* h, float x, const float* wrow){
    u64 xx = dup2(x);
    const ulonglong2* w = (const ulonglong2*)wrow;
    #pragma unroll
    for (int t = 0; t < 4; t++){
        ulonglong2 wv = w[t];
        fma2(h[2*t],   xx, wv.x);
        fma2(h[2*t+1], xx, wv.y);
    }
}

#define ZSTRIDE 68   // 64 cols + 4 pad

__global__ void __launch_bounds__(256, 3)
plane_kernel(const float* __restrict__ g_pos,  const float* __restrict__ g_quat,
             const float* __restrict__ g_xz,   const float* __restrict__ g_aabb,
             const int*   __restrict__ g_widx, const float* __restrict__ g_pls,
             const float* __restrict__ g_w1,   const float* __restrict__ g_b1,
             const float* __restrict__ g_g1,   const float* __restrict__ g_be1,
             const float* __restrict__ g_w2a,  const float* __restrict__ g_b2a,
             const float* __restrict__ g_g2a,  const float* __restrict__ g_be2a,
             const float* __restrict__ g_w2b,  const float* __restrict__ g_b2b,
             const float* __restrict__ g_g2b,  const float* __restrict__ g_be2b,
             const float* __restrict__ g_wout, const float* __restrict__ g_bout,
             float* __restrict__ g_out)
{
    extern __shared__ __align__(16) float smem[];
    float* s_w1  = smem;                 // 79*16 = 1264
    float* s_b1  = smem + 1264;          // 16
    float* s_g1  = smem + 1280;          // 16
    float* s_be1 = smem + 1296;          // 16
    float* s_z   = smem + 1312;          // 8 warps * 32*ZSTRIDE

    const int tid = threadIdx.x;
    for (int i = tid; i < 79*16; i += 256) s_w1[i] = g_w1[i];
    if (tid < 16){ s_b1[tid] = g_b1[tid]; s_g1[tid] = g_g1[tid]; s_be1[tid] = g_be1[tid]; }
    __syncthreads();

    const int warp = tid >> 5, lane = tid & 31;
    const int b = (blockIdx.x << 3) + warp;
    float* sz = s_z + warp * (32*ZSTRIDE);

    const int idx = __ldg(g_widx + b*32 + lane);
    const float* xzb = g_xz + ((size_t)b << 15);   // b * 512 * 64

    // ---- stage all 64 columns of the 32 gathered rows (coalesced LDG.32) ----
    #pragma unroll
    for (int r = 0; r < 32; r++){
        int ir = __shfl_sync(FULL, idx, r);
        const float* src = xzb + (ir << 6);
        sz[r*ZSTRIDE + lane]      = __ldcs(src + lane);
        sz[r*ZSTRIDE + 32 + lane] = __ldcs(src + 32 + lane);
    }

    // ---- pose math overlaps the staging LDG latency ----
    float qx = __ldg(g_quat + b*4 + 0), qy = __ldg(g_quat + b*4 + 1);
    float qz = __ldg(g_quat + b*4 + 2), qw = __ldg(g_quat + b*4 + 3);
    float rn = rsqrtf(qx*qx + qy*qy + qz*qz + qw*qw);
    qx *= rn; qy *= rn; qz *= rn; qw *= rn;
    float r00 = 1.f - 2.f*(qy*qy + qz*qz), r01 = 2.f*(qx*qy - qz*qw), r02 = 2.f*(qx*qz + qy*qw);
    float r10 = 2.f*(qx*qy + qz*qw), r11 = 1.f - 2.f*(qx*qx + qz*qz), r12 = 2.f*(qy*qz - qx*qw);
    float r20 = 2.f*(qx*qz - qy*qw), r21 = 2.f*(qy*qz + qx*qw), r22 = 1.f - 2.f*(qx*qx + qy*qy);

    float px = __ldg(g_pos + b*3 + 0), py = __ldg(g_pos + b*3 + 1), pz = __ldg(g_pos + b*3 + 2);
    float lox = __ldg(g_aabb + b*6 + 0), loy = __ldg(g_aabb + b*6 + 1), loz = __ldg(g_aabb + b*6 + 2);
    float hix = __ldg(g_aabb + b*6 + 3), hiy = __ldg(g_aabb + b*6 + 4), hiz = __ldg(g_aabb + b*6 + 5);

    // voxel center (meshgrid 'ij': n = i*64 + j*8 + k)
    float ci = (float)(idx >> 6)       + 0.5f;
    float cj = (float)((idx >> 3) & 7) + 0.5f;
    float ck = (float)(idx & 7)        + 0.5f;
    float vx = (ci * 0.125f) * (hix - lox) + lox;
    float vy = (cj * 0.125f) * (hiy - loy) + loy;
    float vz = (ck * 0.125f) * (hiz - loz) + loz;
    float e = __expf(__ldg(g_pls));

    u64 h[8];
    #pragma unroll
    for (int t = 0; t < 8; t++) h[t] = *(const u64*)(s_b1 + 2*t);

    acc1(h, r00*vx + r01*vy + r02*vz + px, s_w1 + 0*16);
    acc1(h, r10*vx + r11*vy + r12*vz + py, s_w1 + 1*16);
    acc1(h, r20*vx + r21*vy + r22*vz + pz, s_w1 + 2*16);
    acc1(h, px*e, s_w1 + 67*16);
    acc1(h, py*e, s_w1 + 68*16);
    acc1(h, pz*e, s_w1 + 69*16);
    acc1(h, r00, s_w1 + 70*16);
    acc1(h, r01, s_w1 + 71*16);
    acc1(h, r02, s_w1 + 72*16);
    acc1(h, r10, s_w1 + 73*16);
    acc1(h, r11, s_w1 + 74*16);
    acc1(h, r12, s_w1 + 75*16);
    acc1(h, r20, s_w1 + 76*16);
    acc1(h, r21, s_w1 + 77*16);
    acc1(h, r22, s_w1 + 78*16);

    __syncwarp(FULL);

    // ---- consume 64 xz features (rows 3..66) ----
    const float* row = sz + lane*ZSTRIDE;
    #pragma unroll
    for (int t = 0; t < 16; t++){
        float4 a = *(const float4*)(row + 4*t);
        acc1(h, a.x, s_w1 + (3 + 4*t + 0)*16);
        acc1(h, a.y, s_w1 + (3 + 4*t + 1)*16);
        acc1(h, a.z, s_w1 + (3 + 4*t + 2)*16);
        acc1(h, a.w, s_w1 + (3 + 4*t + 3)*16);
    }

    // ---- relu + LN(16) per lane, x2 ----
    float y[16];
    #pragma unroll
    for (int t = 0; t < 8; t++) upk2(h[t], y[2*t], y[2*t+1]);
    float m = 0.f;
    #pragma unroll
    for (int j = 0; j < 16; j++){ y[j] = fmaxf(y[j], 0.f); m += y[j]; }
    m *= 0.0625f;
    float var = 0.f;
    #pragma unroll
    for (int j = 0; j < 16; j++){ float d = y[j] - m; var += d*d; }
    var *= 0.0625f;
    float is = rsqrtf(var + 1e-6f);
    #pragma unroll
    for (int j = 0; j < 16; j++){
        float t = (y[j] - m) * is * s_g1[j] + s_be1[j];
        y[j] = t + t;                            // z = z + z
    }

    // ---- sum over 32 samples via smem transpose-reduce (sz is free now) ----
    // sample s stores its 16 values at stride 20, upper half offset +16
    // (banks verified conflict-free for both the stores and the two read groups)
    __syncwarp(FULL);
    {
        float* dst = sz + 20*lane + (lane & 16);
        #pragma unroll
        for (int t = 0; t < 4; t++)
            *(float4*)(dst + 4*t) = make_float4(y[4*t], y[4*t+1], y[4*t+2], y[4*t+3]);
    }
    __syncwarp(FULL);
    float v[16];
    {
        const int ch = lane & 15;
        const float* src = sz + (lane & 16) * 21 + ch;   // half*336 + ch
        float p0 = 0.f, p1 = 0.f;
        #pragma unroll
        for (int i = 0; i < 16; i += 2){
            p0 += src[20*i];
            p1 += src[20*(i+1)];
        }
        float p = p0 + p1;
        p += __shfl_xor_sync(FULL, p, 16);               // combine the two halves
        if (lane < 16) sz[680 + ch] = p;                 // publish the 16 sums
    }
    __syncwarp(FULL);
    #pragma unroll
    for (int t = 0; t < 4; t++){
        float4 s4 = *(const float4*)(sz + 680 + 4*t);    // broadcast LDS.128
        v[4*t] = s4.x; v[4*t+1] = s4.y; v[4*t+2] = s4.z; v[4*t+3] = s4.w;
    }

    // ---- head: lane = channel, split accumulators for short chains ----
    {
        float a0 = __ldg(g_b2a + lane), a1 = 0.f, a2 = 0.f, a3 = 0.f;
        #pragma unroll
        for (int i = 0; i < 16; i += 4){
            a0 = fmaf(v[i+0], __ldg(g_w2a + (i+0)*32 + lane), a0);
            a1 = fmaf(v[i+1], __ldg(g_w2a + (i+1)*32 + lane), a1);
            a2 = fmaf(v[i+2], __ldg(g_w2a + (i+2)*32 + lane), a2);
            a3 = fmaf(v[i+3], __ldg(g_w2a + (i+3)*32 + lane), a3);
        }
        float a = (a0 + a1) + (a2 + a3);
        a = fmaxf(a, 0.f);
        float ma = wsum(a) * 0.03125f;
        float da = a - ma;
        float va = wsum(da*da) * 0.03125f;
        float ya = da * rsqrtf(va + 1e-6f) * __ldg(g_g2a + lane) + __ldg(g_be2a + lane);

        float c0 = __ldg(g_b2b + lane), c1 = 0.f, c2 = 0.f, c3 = 0.f;
        #pragma unroll
        for (int i = 0; i < 32; i += 4){
            c0 = fmaf(__shfl_sync(FULL, ya, i+0), __ldg(g_w2b + (i+0)*32 + lane), c0);
            c1 = fmaf(__shfl_sync(FULL, ya, i+1), __ldg(g_w2b + (i+1)*32 + lane), c1);
            c2 = fmaf(__shfl_sync(FULL, ya, i+2), __ldg(g_w2b + (i+2)*32 + lane), c2);
            c3 = fmaf(__shfl_sync(FULL, ya, i+3), __ldg(g_w2b + (i+3)*32 + lane), c3);
        }
        float c = (c0 + c1) + (c2 + c3);
        c = fmaxf(c, 0.f);
        float mc = wsum(c) * 0.03125f;
        float dc = c - mc;
        float vc = wsum(dc*dc) * 0.03125f;
        float yb = dc * rsqrtf(vc + 1e-6f) * __ldg(g_g2b + lane) + __ldg(g_be2b + lane);
        float zf = yb + ya;   // residual

        float o0 = (lane < 13) ? __ldg(g_bout + lane) : 0.f;
        float o1 = 0.f;
        #pragma unroll
        for (int i = 0; i < 32; i += 2){
            float zi0 = __shfl_sync(FULL, zf, i);
            float zi1 = __shfl_sync(FULL, zf, i+1);
            if (lane < 13){
                o0 = fmaf(zi0, __ldg(g_wout + (i  )*13 + lane), o0);
                o1 = fmaf(zi1, __ldg(g_wout + (i+1)*13 + lane), o1);
            }
        }
        if (lane < 13) g_out[b*13 + lane] = tanhf(o0 + o1);
    }
}

extern "C" void kernel_launch(void* const* d_in, const int* in_sizes, int n_in,
                              void* d_out, int out_size)
{
    (void)in_sizes; (void)n_in; (void)out_size;
    const int SMEM_BYTES = (1312 + 8*32*ZSTRIDE) * 4;   // ~73.1 KB (3 blocks/SM)
    cudaFuncSetAttribute(plane_kernel,
                         cudaFuncAttributeMaxDynamicSharedMemorySize, SMEM_BYTES);
    plane_kernel<<<1024, 256, SMEM_BYTES>>>(
        (const float*)d_in[0],  (const float*)d_in[1],  (const float*)d_in[2],
        (const float*)d_in[3],  (const int*)  d_in[4],  (const float*)d_in[5],
        (const float*)d_in[6],  (const float*)d_in[7],  (const float*)d_in[8],
        (const float*)d_in[9],  (const float*)d_in[10], (const float*)d_in[11],
        (const float*)d_in[12], (const float*)d_in[13], (const float*)d_in[14],
        (const float*)d_in[15], (const float*)d_in[16], (const float*)d_in[17],
        (const float*)d_in[18], (const float*)d_in[19],
        (float*)d_out);
}

// round 9
// speedup vs baseline: 2.0649x; 1.0715x over previous
#include <cuda_runtime.h>
#include <cstdint>

// PlaneModel: B=8192, NS=32, P=64, HID1=16, BASE=32, OUT=13, D_IN=79
// Layer-1 GEMV on mma.sync tf32 (3xTF32 split). warp = batch: 32 rows x 16 ch x K80.
#define FULL 0xffffffffu
#define ZS 84        // A staging stride (floats): frag reads conflict-free ((20r+c) mod 32)
#define BSTR 24      // B table stride: frag reads conflict-free ((24j+8nt+gr) mod 32)

__device__ __forceinline__ uint32_t f2tf(float x){
    uint32_t r; asm("cvt.rna.tf32.f32 %0, %1;" : "=r"(r) : "f"(x)); return r;
}
__device__ __forceinline__ void mma8(float* d, const uint32_t* a, const uint32_t* b){
    asm volatile("mma.sync.aligned.m16n8k8.row.col.f32.tf32.tf32.f32 "
        "{%0,%1,%2,%3},{%4,%5,%6,%7},{%8,%9},{%0,%1,%2,%3};"
        : "+f"(d[0]), "+f"(d[1]), "+f"(d[2]), "+f"(d[3])
        : "r"(a[0]), "r"(a[1]), "r"(a[2]), "r"(a[3]), "r"(b[0]), "r"(b[1]));
}
__device__ __forceinline__ float wsum(float x){
    x += __shfl_xor_sync(FULL, x, 16);
    x += __shfl_xor_sync(FULL, x, 8);
    x += __shfl_xor_sync(FULL, x, 4);
    x += __shfl_xor_sync(FULL, x, 2);
    x += __shfl_xor_sync(FULL, x, 1);
    return x;
}

__global__ void __launch_bounds__(256)
plane_kernel(const float* __restrict__ g_pos,  const float* __restrict__ g_quat,
             const float* __restrict__ g_xz,   const float* __restrict__ g_aabb,
             const int*   __restrict__ g_widx, const float* __restrict__ g_pls,
             const float* __restrict__ g_w1,   const float* __restrict__ g_b1,
             const float* __restrict__ g_g1,   const float* __restrict__ g_be1,
             const float* __restrict__ g_w2a,  const float* __restrict__ g_b2a,
             const float* __restrict__ g_g2a,  const float* __restrict__ g_be2a,
             const float* __restrict__ g_w2b,  const float* __restrict__ g_b2b,
             const float* __restrict__ g_g2b,  const float* __restrict__ g_be2b,
             const float* __restrict__ g_wout, const float* __restrict__ g_bout,
             float* __restrict__ g_out)
{
    extern __shared__ __align__(16) float smem[];
    float* s_bh = smem;                 // 80*24 tf32(hi) weights  [k][n]
    float* s_bl = s_bh + 80*BSTR;       // 80*24 tf32(lo)
    float* s_v  = s_bl + 80*BSTR;       // 8*16 per-warp layer-1 sums
    float* s_z  = s_v + 128;            // 8 * 32*ZS  A staging

    const int tid  = threadIdx.x;
    const int warp = tid >> 5, lane = tid & 31;
    const int j    = lane & 3;          // threadID in quad
    const int gr   = lane >> 2;         // group id 0..7
    const int b    = (blockIdx.x << 3) + warp;
    float* szw = s_z + warp*(32*ZS);

    // ---- build W hi/lo tf32 tables (feature-permuted: xz 0..63, pick 64..66, pose 67..78, 79=0)
    for (int e = tid; e < 1280; e += 256){
        int k = e >> 4, n = e & 15;
        float w = 0.f;
        if (k < 79){
            int f = (k < 64) ? k + 3 : ((k < 67) ? k - 64 : k);
            w = __ldg(g_w1 + f*16 + n);
        }
        uint32_t hi = f2tf(w);
        float lo = w - __uint_as_float(hi);
        s_bh[k*BSTR + n] = __uint_as_float(hi);
        s_bl[k*BSTR + n] = __uint_as_float(f2tf(lo));
    }

    // ---- stage A: xz gather to cols 0..63 (coalesced LDG.32, conflict-free STS)
    const int idx = __ldg(g_widx + b*32 + lane);
    const float* xzb = g_xz + ((size_t)b << 15);
    #pragma unroll
    for (int r = 0; r < 32; r++){
        int ir = __shfl_sync(FULL, idx, r);
        const float* src = xzb + (ir << 6);
        szw[r*ZS + lane]      = __ldcs(src + lane);
        szw[r*ZS + 32 + lane] = __ldcs(src + 32 + lane);
    }

    // ---- pose features for this lane's sample -> cols 64..79 (row = lane)
    {
        float qx = __ldg(g_quat + b*4 + 0), qy = __ldg(g_quat + b*4 + 1);
        float qz = __ldg(g_quat + b*4 + 2), qw = __ldg(g_quat + b*4 + 3);
        float rn = rsqrtf(qx*qx + qy*qy + qz*qz + qw*qw);
        qx *= rn; qy *= rn; qz *= rn; qw *= rn;
        float r00 = 1.f - 2.f*(qy*qy + qz*qz), r01 = 2.f*(qx*qy - qz*qw), r02 = 2.f*(qx*qz + qy*qw);
        float r10 = 2.f*(qx*qy + qz*qw), r11 = 1.f - 2.f*(qx*qx + qz*qz), r12 = 2.f*(qy*qz - qx*qw);
        float r20 = 2.f*(qx*qz - qy*qw), r21 = 2.f*(qy*qz + qx*qw), r22 = 1.f - 2.f*(qx*qx + qy*qy);
        float px = __ldg(g_pos + b*3 + 0), py = __ldg(g_pos + b*3 + 1), pz = __ldg(g_pos + b*3 + 2);
        float lox = __ldg(g_aabb + b*6 + 0), loy = __ldg(g_aabb + b*6 + 1), loz = __ldg(g_aabb + b*6 + 2);
        float hix = __ldg(g_aabb + b*6 + 3), hiy = __ldg(g_aabb + b*6 + 4), hiz = __ldg(g_aabb + b*6 + 5);
        float ci = (float)(idx >> 6) + 0.5f, cj = (float)((idx >> 3) & 7) + 0.5f, ck = (float)(idx & 7) + 0.5f;
        float vx = (ci*0.125f)*(hix - lox) + lox;
        float vy = (cj*0.125f)*(hiy - loy) + loy;
        float vz = (ck*0.125f)*(hiz - loz) + loz;
        float e = __expf(__ldg(g_pls));
        float* prow = szw + lane*ZS;
        prow[64] = r00*vx + r01*vy + r02*vz + px;
        prow[65] = r10*vx + r11*vy + r12*vz + py;
        prow[66] = r20*vx + r21*vy + r22*vz + pz;
        prow[67] = px*e; prow[68] = py*e; prow[69] = pz*e;
        prow[70] = r00; prow[71] = r01; prow[72] = r02;
        prow[73] = r10; prow[74] = r11; prow[75] = r12;
        prow[76] = r20; prow[77] = r21; prow[78] = r22;
        prow[79] = 0.f;
    }
    __syncthreads();

    // ---- 3xTF32 MMA: D[2 mtiles][2 ntiles][4]
    float d[2][2][4];
    #pragma unroll
    for (int mt = 0; mt < 2; mt++)
        #pragma unroll
        for (int nt = 0; nt < 2; nt++)
            #pragma unroll
            for (int q = 0; q < 4; q++) d[mt][nt][q] = 0.f;

    #pragma unroll
    for (int k0 = 0; k0 < 10; k0++){
        const int kA = k0*8 + j;
        uint32_t bh[2][2], bl[2][2];
        #pragma unroll
        for (int nt = 0; nt < 2; nt++){
            bh[nt][0] = __float_as_uint(s_bh[(kA  )*BSTR + nt*8 + gr]);
            bh[nt][1] = __float_as_uint(s_bh[(kA+4)*BSTR + nt*8 + gr]);
            bl[nt][0] = __float_as_uint(s_bl[(kA  )*BSTR + nt*8 + gr]);
            bl[nt][1] = __float_as_uint(s_bl[(kA+4)*BSTR + nt*8 + gr]);
        }
        #pragma unroll
        for (int mt = 0; mt < 2; mt++){
            const float* base = szw + (mt*16 + gr)*ZS + kA;
            float a0 = base[0];
            float a1 = base[8*ZS];
            float a2 = base[4];
            float a3 = base[8*ZS + 4];
            uint32_t ah[4] = { f2tf(a0), f2tf(a1), f2tf(a2), f2tf(a3) };
            uint32_t al[4] = { f2tf(a0 - __uint_as_float(ah[0])),
                               f2tf(a1 - __uint_as_float(ah[1])),
                               f2tf(a2 - __uint_as_float(ah[2])),
                               f2tf(a3 - __uint_as_float(ah[3])) };
            #pragma unroll
            for (int nt = 0; nt < 2; nt++){
                mma8(d[mt][nt], ah, bh[nt]);
                mma8(d[mt][nt], al, bh[nt]);
                mma8(d[mt][nt], ah, bl[nt]);
            }
        }
    }

    // ---- epilogue: bias + relu + LN(16) per sample (quad shfl), x2, sum over samples
    // lane's 4 channels: 2j, 2j+1, 8+2j, 9+2j
    float b1v[4] = { __ldg(g_b1 + 2*j),  __ldg(g_b1 + 2*j + 1),
                     __ldg(g_b1 + 8 + 2*j), __ldg(g_b1 + 9 + 2*j) };
    float g1v[4] = { __ldg(g_g1 + 2*j),  __ldg(g_g1 + 2*j + 1),
                     __ldg(g_g1 + 8 + 2*j), __ldg(g_g1 + 9 + 2*j) };
    float be1v[4] = { __ldg(g_be1 + 2*j), __ldg(g_be1 + 2*j + 1),
                      __ldg(g_be1 + 8 + 2*j), __ldg(g_be1 + 9 + 2*j) };

    float vsum[4] = {0.f, 0.f, 0.f, 0.f};
    #pragma unroll
    for (int mt = 0; mt < 2; mt++){
        #pragma unroll
        for (int rl = 0; rl < 2; rl++){
            float y0 = fmaxf(d[mt][0][rl*2]   + b1v[0], 0.f);
            float y1 = fmaxf(d[mt][0][rl*2+1] + b1v[1], 0.f);
            float y2 = fmaxf(d[mt][1][rl*2]   + b1v[2], 0.f);
            float y3 = fmaxf(d[mt][1][rl*2+1] + b1v[3], 0.f);
            float s = (y0 + y1) + (y2 + y3);
            s += __shfl_xor_sync(FULL, s, 1);
            s += __shfl_xor_sync(FULL, s, 2);
            float m = s * 0.0625f;
            float q0 = y0 - m, q1 = y1 - m, q2 = y2 - m, q3 = y3 - m;
            float q = (q0*q0 + q1*q1) + (q2*q2 + q3*q3);
            q += __shfl_xor_sync(FULL, q, 1);
            q += __shfl_xor_sync(FULL, q, 2);
            float is2 = 2.f * rsqrtf(q * 0.0625f + 1e-6f);   // LN then z+z
            vsum[0] += q0 * is2 * g1v[0] + 2.f*be1v[0];
            vsum[1] += q1 * is2 * g1v[1] + 2.f*be1v[1];
            vsum[2] += q2 * is2 * g1v[2] + 2.f*be1v[2];
            vsum[3] += q3 * is2 * g1v[3] + 2.f*be1v[3];
        }
    }
    #pragma unroll
    for (int c = 0; c < 4; c++){
        vsum[c] += __shfl_xor_sync(FULL, vsum[c], 4);
        vsum[c] += __shfl_xor_sync(FULL, vsum[c], 8);
        vsum[c] += __shfl_xor_sync(FULL, vsum[c], 16);
    }
    if (gr == 0){
        float* sv = s_v + warp*16;
        sv[2*j]     = vsum[0];
        sv[2*j + 1] = vsum[1];
        sv[8 + 2*j] = vsum[2];
        sv[9 + 2*j] = vsum[3];
    }
    __syncwarp(FULL);
    float v[16];
    #pragma unroll
    for (int t = 0; t < 4; t++){
        float4 s4 = *(const float4*)(s_v + warp*16 + 4*t);
        v[4*t] = s4.x; v[4*t+1] = s4.y; v[4*t+2] = s4.z; v[4*t+3] = s4.w;
    }

    // ---- head: lane = channel ----
    {
        float a0 = __ldg(g_b2a + lane), a1 = 0.f, a2 = 0.f, a3 = 0.f;
        #pragma unroll
        for (int i = 0; i < 16; i += 4){
            a0 = fmaf(v[i+0], __ldg(g_w2a + (i+0)*32 + lane), a0);
            a1 = fmaf(v[i+1], __ldg(g_w2a + (i+1)*32 + lane), a1);
            a2 = fmaf(v[i+2], __ldg(g_w2a + (i+2)*32 + lane), a2);
            a3 = fmaf(v[i+3], __ldg(g_w2a + (i+3)*32 + lane), a3);
        }
        float a = (a0 + a1) + (a2 + a3);
        a = fmaxf(a, 0.f);
        float ma = wsum(a) * 0.03125f;
        float da = a - ma;
        float va = wsum(da*da) * 0.03125f;
        float ya = da * rsqrtf(va + 1e-6f) * __ldg(g_g2a + lane) + __ldg(g_be2a + lane);

        float c0 = __ldg(g_b2b + lane), c1 = 0.f, c2 = 0.f, c3 = 0.f;
        #pragma unroll
        for (int i = 0; i < 32; i += 4){
            c0 = fmaf(__shfl_sync(FULL, ya, i+0), __ldg(g_w2b + (i+0)*32 + lane), c0);
            c1 = fmaf(__shfl_sync(FULL, ya, i+1), __ldg(g_w2b + (i+1)*32 + lane), c1);
            c2 = fmaf(__shfl_sync(FULL, ya, i+2), __ldg(g_w2b + (i+2)*32 + lane), c2);
            c3 = fmaf(__shfl_sync(FULL, ya, i+3), __ldg(g_w2b + (i+3)*32 + lane), c3);
        }
        float c = (c0 + c1) + (c2 + c3);
        c = fmaxf(c, 0.f);
        float mc = wsum(c) * 0.03125f;
        float dc = c - mc;
        float vc = wsum(dc*dc) * 0.03125f;
        float yb = dc * rsqrtf(vc + 1e-6f) * __ldg(g_g2b + lane) + __ldg(g_be2b + lane);
        float zf = yb + ya;   // residual

        float o0 = (lane < 13) ? __ldg(g_bout + lane) : 0.f;
        float o1 = 0.f;
        #pragma unroll
        for (int i = 0; i < 32; i += 2){
            float zi0 = __shfl_sync(FULL, zf, i);
            float zi1 = __shfl_sync(FULL, zf, i+1);
            if (lane < 13){
                o0 = fmaf(zi0, __ldg(g_wout + (i  )*13 + lane), o0);
                o1 = fmaf(zi1, __ldg(g_wout + (i+1)*13 + lane), o1);
            }
        }
        if (lane < 13) g_out[b*13 + lane] = tanhf(o0 + o1);
    }
}

extern "C" void kernel_launch(void* const* d_in, const int* in_sizes, int n_in,
                              void* d_out, int out_size)
{
    (void)in_sizes; (void)n_in; (void)out_size;
    const int SMEM_BYTES = (80*BSTR*2 + 128 + 8*32*ZS) * 4;   // ~101.9 KB
    cudaFuncSetAttribute(plane_kernel,
                         cudaFuncAttributeMaxDynamicSharedMemorySize, SMEM_BYTES);
    plane_kernel<<<1024, 256, SMEM_BYTES>>>(
        (const float*)d_in[0],  (const float*)d_in[1],  (const float*)d_in[2],
        (const float*)d_in[3],  (const int*)  d_in[4],  (const float*)d_in[5],
        (const float*)d_in[6],  (const float*)d_in[7],  (const float*)d_in[8],
        (const float*)d_in[9],  (const float*)d_in[10], (const float*)d_in[11],
        (const float*)d_in[12], (const float*)d_in[13], (const float*)d_in[14],
        (const float*)d_in[15], (const float*)d_in[16], (const float*)d_in[17],
        (const float*)d_in[18], (const float*)d_in[19],
        (float*)d_out);
}